// round 15
// baseline (speedup 1.0000x reference)
#include <cuda_runtime.h>
#include <cuda_fp16.h>
#include <math.h>
#include <stdint.h>

// R15: R14 structure (phased levels 6-18 with 0-5 piggyback; mlp kernel does
// level 19 inline + MLP) with the MLP kernel processing TWO points per thread.
// R14's mlp measured 108.7us at issue=35.6%, occ=35%: latency-exposed on the
// LDS.128 weight stream (640/thread for W1). Two points amortize every weight
// load over two feature vectors (LDS/point halves) and double FMA ILP.
// Per-point accumulation order unchanged -> rel_err stays 6.8627e-4.

#define NLVL   20
#define LOG2T  24
#define TMASK  ((1u << LOG2T) - 1u)
#define PRIME1 2654435761u
#define PRIME2 805459861u
#define INDIM  40
#define HID    64
#define NPTS   524288

struct ResParams { float r[NLVL]; };

__device__ __half2 g_feat[NLVL * NPTS];   // level-major scratch (42 MB)

__device__ __forceinline__ float h_rt(float v) {
    return __half2float(__float2half_rn(v));
}

__device__ __forceinline__ bool probe_f32(const void* W2_) {
    const float* w2p = (const float*)W2_;
    int votes = 0;
    #pragma unroll
    for (int i = 0; i < 8; ++i) {
        const float v = __ldg(w2p + i);
        if (isfinite(v) && fabsf(v) >= 2e-3f && fabsf(v) <= 8.0f) ++votes;
    }
    return votes >= 4;
}

// ---- f32x2 packed helpers (FFMA2) ----
__device__ __forceinline__ uint64_t pk2(float lo, float hi) {
    uint64_t r; asm("mov.b64 %0, {%1,%2};" : "=l"(r) : "f"(lo), "f"(hi)); return r;
}
__device__ __forceinline__ float2 upk2(uint64_t v) {
    float2 f; asm("mov.b64 {%0,%1}, %2;" : "=f"(f.x), "=f"(f.y) : "l"(v)); return f;
}
__device__ __forceinline__ void ffma2(uint64_t& d, uint64_t a, uint64_t b) {
    asm("fma.rn.f32x2 %0, %1, %2, %0;" : "+l"(d) : "l"(a), "l"(b));
}

// ---- one level's gather+interp (bit-identical reference fp16 chain) ----
__device__ __forceinline__ __half2 encode_level(
    float px, float py, float pz, float rf,
    const void* __restrict__ table_, int li, bool f32mode)
{
    const float fx = px * rf, fy = py * rf, fz = pz * rf;
    const float gx = floorf(fx), gy = floorf(fy), gz = floorf(fz);
    const float dx = fx - gx, dy = fy - gy, dz = fz - gz;
    const unsigned bx = (unsigned)gx;
    const unsigned by = (unsigned)gy;
    const unsigned bz = (unsigned)gz;
    const unsigned hy0 = by * PRIME1, hy1 = hy0 + PRIME1;
    const unsigned hz0 = bz * PRIME2, hz1 = hz0 + PRIME2;
    const unsigned bx1 = bx + 1u;

    const unsigned i0 = (bx  ^ hy0 ^ hz0) & TMASK;
    const unsigned i1 = (bx1 ^ hy0 ^ hz0) & TMASK;
    const unsigned i2 = (bx  ^ hy1 ^ hz0) & TMASK;
    const unsigned i3 = (bx1 ^ hy1 ^ hz0) & TMASK;
    const unsigned i4 = (bx  ^ hy0 ^ hz1) & TMASK;
    const unsigned i5 = (bx1 ^ hy0 ^ hz1) & TMASK;
    const unsigned i6 = (bx  ^ hy1 ^ hz1) & TMASK;
    const unsigned i7 = (bx1 ^ hy1 ^ hz1) & TMASK;

    __half2 t0, t1, t2, t3, t4, t5, t6, t7;
    if (f32mode) {
        const float2* __restrict__ tb = (const float2*)table_ + ((size_t)li << LOG2T);
        const float2 f0 = __ldg(tb + i0);
        const float2 f1 = __ldg(tb + i1);
        const float2 f2 = __ldg(tb + i2);
        const float2 f3 = __ldg(tb + i3);
        const float2 f4 = __ldg(tb + i4);
        const float2 f5 = __ldg(tb + i5);
        const float2 f6 = __ldg(tb + i6);
        const float2 f7 = __ldg(tb + i7);
        t0 = __floats2half2_rn(f0.x, f0.y);
        t1 = __floats2half2_rn(f1.x, f1.y);
        t2 = __floats2half2_rn(f2.x, f2.y);
        t3 = __floats2half2_rn(f3.x, f3.y);
        t4 = __floats2half2_rn(f4.x, f4.y);
        t5 = __floats2half2_rn(f5.x, f5.y);
        t6 = __floats2half2_rn(f6.x, f6.y);
        t7 = __floats2half2_rn(f7.x, f7.y);
    } else {
        const __half2* __restrict__ tb = (const __half2*)table_ + ((size_t)li << LOG2T);
        t0 = __ldg(tb + i0);  t1 = __ldg(tb + i1);
        t2 = __ldg(tb + i2);  t3 = __ldg(tb + i3);
        t4 = __ldg(tb + i4);  t5 = __ldg(tb + i5);
        t6 = __ldg(tb + i6);  t7 = __ldg(tb + i7);
    }

    const float ox = 1.f - dx, oy = 1.f - dy, oz = 1.f - dz;

    __half2 acc =              __hmul2(__float2half2_rn((ox * oy) * oz), t0);
    acc = __hadd2(acc, __hmul2(__float2half2_rn((dx * oy) * oz), t1));
    acc = __hadd2(acc, __hmul2(__float2half2_rn((ox * dy) * oz), t2));
    acc = __hadd2(acc, __hmul2(__float2half2_rn((dx * dy) * oz), t3));
    acc = __hadd2(acc, __hmul2(__float2half2_rn((ox * oy) * dz), t4));
    acc = __hadd2(acc, __hmul2(__float2half2_rn((dx * oy) * dz), t5));
    acc = __hadd2(acc, __hmul2(__float2half2_rn((ox * dy) * dz), t6));
    acc = __hadd2(acc, __hmul2(__float2half2_rn((dx * dy) * dz), t7));
    return acc;
}

// -------- levels 6..18 bid-phased; groups 6..11 piggyback levels 0..5 --------
__global__ __launch_bounds__(256) void k_enc_phased(
    const float* __restrict__ xin,
    const void*  __restrict__ table_,
    const void*  __restrict__ W2_,
    int l0, int bpl, int n, ResParams rp)
{
    const int li = l0 + blockIdx.x / bpl;
    const int pt = (blockIdx.x % bpl) * 256 + threadIdx.x;
    if (pt >= n) return;
    const bool f32mode = probe_f32(W2_);

    const float px = __ldg(xin + 3 * pt + 0);
    const float py = __ldg(xin + 3 * pt + 1);
    const float pz = __ldg(xin + 3 * pt + 2);

    const __half2 acc = encode_level(px, py, pz, rp.r[li], table_, li, f32mode);
    __stcs(&g_feat[(size_t)li * NPTS + pt], acc);

    if (li < 12) {    // piggyback cache-resident level li-6 under DRAM stalls
        const int lo = li - 6;
        const __half2 acc2 = encode_level(px, py, pz, rp.r[lo], table_, lo, f32mode);
        __stcs(&g_feat[(size_t)lo * NPTS + pt], acc2);
    }
}

// -------- final: level 19 inline + MLP, TWO points per thread --------
__global__ __launch_bounds__(256) void k_mlp_final(
    const float* __restrict__ xin,
    const void*  __restrict__ table_,
    const void*  __restrict__ W1_,
    const void*  __restrict__ W2_,
    void*        __restrict__ out_,
    int n, ResParams rp)
{
    __shared__ __align__(16) float W1f[INDIM * HID];
    __shared__ __align__(16) float W2f[HID * 4];

    const bool f32mode = probe_f32(W2_);

    if (f32mode) {
        const float* W1s = (const float*)W1_;
        const float* W2s = (const float*)W2_;
        for (int i = threadIdx.x; i < INDIM * HID; i += 256) W1f[i] = W1s[i];
        for (int i = threadIdx.x; i < HID * 4;   i += 256) W2f[i] = W2s[i];
    } else {
        const __half* W1s = (const __half*)W1_;
        const __half* W2s = (const __half*)W2_;
        for (int i = threadIdx.x; i < INDIM * HID; i += 256) W1f[i] = __half2float(W1s[i]);
        for (int i = threadIdx.x; i < HID * 4;   i += 256) W2f[i] = __half2float(W2s[i]);
    }
    __syncthreads();

    const int ptA = blockIdx.x * 512 + threadIdx.x;
    const int ptB = ptA + 256;
    if (ptA >= n) return;
    const bool hasB = (ptB < n);
    const int ptBs = hasB ? ptB : ptA;     // safe index for B's loads

    const float pxA = __ldg(xin + 3 * ptA + 0);
    const float pyA = __ldg(xin + 3 * ptA + 1);
    const float pzA = __ldg(xin + 3 * ptA + 2);
    const float pxB = __ldg(xin + 3 * ptBs + 0);
    const float pyB = __ldg(xin + 3 * ptBs + 1);
    const float pzB = __ldg(xin + 3 * ptBs + 2);

    __half2 featA[NLVL], featB[NLVL];
    featA[19] = encode_level(pxA, pyA, pzA, rp.r[19], table_, 19, f32mode);
    featB[19] = encode_level(pxB, pyB, pzB, rp.r[19], table_, 19, f32mode);
    #pragma unroll
    for (int l = 0; l < 19; ++l) {
        featA[l] = __ldcs(&g_feat[(size_t)l * NPTS + ptA]);
        featB[l] = __ldcs(&g_feat[(size_t)l * NPTS + ptBs]);
    }

    // MLP for both points; weight loads shared, per-point accumulation order
    // identical to R8-R14 (rel_err 6.8627e-4).
    float ohA[2][4], ohB[2][4];
    #pragma unroll
    for (int h = 0; h < 2; ++h) {
        const int hbase = h * 32;
        uint64_t oA01 = pk2(0.f, 0.f), oA23 = pk2(0.f, 0.f);
        uint64_t oB01 = pk2(0.f, 0.f), oB23 = pk2(0.f, 0.f);

        #pragma unroll 1
        for (int cb = 0; cb < 32; cb += 8) {
            uint64_t hA[4], hB[4];
            #pragma unroll
            for (int j2 = 0; j2 < 4; ++j2) { hA[j2] = pk2(0.f, 0.f); hB[j2] = pk2(0.f, 0.f); }

            #pragma unroll
            for (int lp = 0; lp < NLVL; ++lp) {
                const float2 fvA = __half22float2(featA[lp]);
                const float2 fvB = __half22float2(featB[lp]);
                const uint64_t fAx = pk2(fvA.x, fvA.x), fAy = pk2(fvA.y, fvA.y);
                const uint64_t fBx = pk2(fvB.x, fvB.x), fBy = pk2(fvB.y, fvB.y);
                const ulonglong2* __restrict__ w0p =
                    (const ulonglong2*)&W1f[(2 * lp)     * HID + hbase + cb];
                const ulonglong2* __restrict__ w1p =
                    (const ulonglong2*)&W1f[(2 * lp + 1) * HID + hbase + cb];
                const ulonglong2 a0 = w0p[0], a1 = w0p[1];
                const ulonglong2 b0 = w1p[0], b1 = w1p[1];
                ffma2(hA[0], fAx, a0.x);  ffma2(hA[0], fAy, b0.x);
                ffma2(hA[1], fAx, a0.y);  ffma2(hA[1], fAy, b0.y);
                ffma2(hA[2], fAx, a1.x);  ffma2(hA[2], fAy, b1.x);
                ffma2(hA[3], fAx, a1.y);  ffma2(hA[3], fAy, b1.y);
                ffma2(hB[0], fBx, a0.x);  ffma2(hB[0], fBy, b0.x);
                ffma2(hB[1], fBx, a0.y);  ffma2(hB[1], fBy, b0.y);
                ffma2(hB[2], fBx, a1.x);  ffma2(hB[2], fBy, b1.x);
                ffma2(hB[3], fBx, a1.y);  ffma2(hB[3], fBy, b1.y);
            }

            #pragma unroll
            for (int j2 = 0; j2 < 4; ++j2) {
                const float2 hpA = upk2(hA[j2]);
                const float2 hpB = upk2(hB[j2]);
                #pragma unroll
                for (int k = 0; k < 2; ++k) {
                    const int jj = 2 * j2 + k;
                    const ulonglong2 w2 =
                        *(const ulonglong2*)&W2f[(hbase + cb + jj) * 4];
                    const float hvA = h_rt(fmaxf(k ? hpA.y : hpA.x, 0.f));
                    const float hvB = h_rt(fmaxf(k ? hpB.y : hpB.x, 0.f));
                    const uint64_t hA2 = pk2(hvA, hvA);
                    const uint64_t hB2 = pk2(hvB, hvB);
                    ffma2(oA01, hA2, w2.x);
                    ffma2(oA23, hA2, w2.y);
                    ffma2(oB01, hB2, w2.x);
                    ffma2(oB23, hB2, w2.y);
                }
            }
        }
        const float2 aA01 = upk2(oA01), aA23 = upk2(oA23);
        const float2 aB01 = upk2(oB01), aB23 = upk2(oB23);
        ohA[h][0] = aA01.x; ohA[h][1] = aA01.y; ohA[h][2] = aA23.x; ohA[h][3] = aA23.y;
        ohB[h][0] = aB01.x; ohB[h][1] = aB01.y; ohB[h][2] = aB23.x; ohB[h][3] = aB23.y;
    }

    const float oA0 = ohA[0][0] + ohA[1][0];
    const float oA1 = ohA[0][1] + ohA[1][1];
    const float oA2 = ohA[0][2] + ohA[1][2];
    const float oA3 = ohA[0][3] + ohA[1][3];
    const float oB0 = ohB[0][0] + ohB[1][0];
    const float oB1 = ohB[0][1] + ohB[1][1];
    const float oB2 = ohB[0][2] + ohB[1][2];
    const float oB3 = ohB[0][3] + ohB[1][3];

    if (f32mode) {
        float4* o = (float4*)out_;
        o[ptA] = make_float4(h_rt(oA0), h_rt(oA1), h_rt(oA2), h_rt(oA3));
        if (hasB)
            o[ptB] = make_float4(h_rt(oB0), h_rt(oB1), h_rt(oB2), h_rt(oB3));
    } else {
        __half2* o = (__half2*)out_;
        o[2 * ptA + 0] = __halves2half2(__float2half_rn(oA0), __float2half_rn(oA1));
        o[2 * ptA + 1] = __halves2half2(__float2half_rn(oA2), __float2half_rn(oA3));
        if (hasB) {
            o[2 * ptB + 0] = __halves2half2(__float2half_rn(oB0), __float2half_rn(oB1));
            o[2 * ptB + 1] = __halves2half2(__float2half_rn(oB2), __float2half_rn(oB3));
        }
    }
}

extern "C" void kernel_launch(void* const* d_in, const int* in_sizes, int n_in,
                              void* d_out, int out_size) {
    const float* x     = nullptr;  int x_elems = 0;
    const void*  table = nullptr;
    const void*  W1    = nullptr;
    const void*  W2    = nullptr;

    for (int i = 0; i < n_in; ++i) {
        const long long sz = in_sizes[i];
        if (sz == 671088640LL)      table = d_in[i];
        else if (sz == 1572864LL) { x = (const float*)d_in[i]; x_elems = (int)sz; }
        else if (sz == 2560LL)      W1 = d_in[i];
        else if (sz == 256LL)       W2 = d_in[i];
    }
    for (int i = 0; i < n_in; ++i) {
        const long long sz = in_sizes[i];
        if (!table && sz > 100000000LL) table = d_in[i];
        else if (!x && sz > 100000LL && sz <= 100000000LL) { x = (const float*)d_in[i]; x_elems = (int)sz; }
        else if (!W1 && sz > 1000LL && sz <= 100000LL) W1 = d_in[i];
        else if (!W2 && sz <= 1000LL) W2 = d_in[i];
    }

    int n = x_elems / 3;
    if (n > NPTS) n = NPTS;

    ResParams rp;
    for (int l = 0; l < NLVL; ++l)
        rp.r[l] = (float)floor(16.0 * pow(1.3819, (double)l));

    const int bpl  = (n + 255) / 256;    // blocks per level (2048)
    const int bpl2 = (n + 511) / 512;    // mlp blocks, 2 pts/thread (1024)

    k_enc_phased<<<13 * bpl, 256>>>(x, table, W2, 6, bpl, n, rp);  // lv 6-18 (+0-5)
    k_mlp_final<<<bpl2, 256>>>(x, table, W1, W2, d_out, n, rp);    // lv 19 + MLP x2
}